// round 14
// baseline (speedup 1.0000x reference)
#include <cuda_runtime.h>

// Problem constants (from reference)
#define NN 64
#define CC 256
#define EMBED 16
#define INDEX_K 16              // ceil(256^0.5) = 16
#define HW4 784                 // float4 per (n,c) slab (56*56/4)
#define SCALE (256.0f / 240.0f) // c / (c - INDEX)

// One block per (n,c) slab. Warp-specialized, NO block-wide barrier:
//  - warp 0: mask FIRST (8 channels/lane, 32x LDG.128 of the L1-hot table),
//    publish m via volatile smem, THEN stream its own 1/8 of the slab.
//    (mask accums and stream float4s never live together -> low regs)
//  - warps 1..7: front-batch DRAM loads, nanosleep-spin on the smem flag,
//    then scale+store. Stores gated only by own loads.
// Flag value = blockIdx.x: stale values never match within a launch; a
// cross-replay match delivers the identical call-invariant m (benign).
__global__ void __launch_bounds__(256)
fused_kernel(const float4* __restrict__ x,
             const float* __restrict__ embeds,
             const float* __restrict__ table,
             float4* __restrict__ out) {
    __shared__ volatile unsigned s_flag;
    __shared__ volatile float s_m;

    const int nc = blockIdx.x;
    const int n = nc >> 8;       // sample
    const int c = nc & 255;      // this block's channel
    const int t = threadIdx.x;
    const int wid = t >> 5;
    const int lane = t & 31;

    const long long base = (long long)nc * HW4;
    const float4* __restrict__ xin = x + base;
    float4* __restrict__ o = out + base;

    if (wid == 0) {
        // ---- warp 0: mask first (no x-loads live yet) ----
        float a0 = 0.f, a1 = 0.f, a2 = 0.f, a3 = 0.f;
        float a4 = 0.f, a5 = 0.f, a6 = 0.f, a7 = 0.f;
        const float4* __restrict__ tab4 = (const float4*)table;  // [16][64]
        const float* __restrict__ emb = embeds + n * EMBED;
#pragma unroll
        for (int e = 0; e < EMBED; ++e) {
            const float w = __ldg(emb + e);                   // uniform
            const float4 t0 = __ldg(tab4 + e * 64 + lane * 2);
            const float4 t1 = __ldg(tab4 + e * 64 + lane * 2 + 1);
            a0 += w * t0.x; a1 += w * t0.y; a2 += w * t0.z; a3 += w * t0.w;
            a4 += w * t1.x; a5 += w * t1.y; a6 += w * t1.z; a7 += w * t1.w;
        }
        // activ[c] lives in lane (c>>3), slot (c&7)
        const int ks = c & 7;
        float av = (ks == 0) ? a0 : (ks == 1) ? a1 : (ks == 2) ? a2 : (ks == 3) ? a3
                 : (ks == 4) ? a4 : (ks == 5) ? a5 : (ks == 6) ? a6 : a7;
        const float ac = __shfl_sync(0xffffffffu, av, c >> 3);
        // keep <=> #{j: activ[j] <= activ[c]} >= INDEX_K+1 (tie-safe)
        int cnt8 = (a0 <= ac) + (a1 <= ac) + (a2 <= ac) + (a3 <= ac)
                 + (a4 <= ac) + (a5 <= ac) + (a6 <= ac) + (a7 <= ac);
        const int cnt = __reduce_add_sync(0xffffffffu, cnt8);
        const float m = (cnt >= INDEX_K + 1) ? SCALE : 0.0f;
        if (lane == 0) {
            s_m = m;
            __threadfence_block();
            s_flag = (unsigned)nc;
        }
        // ---- now stream warp 0's share (t in [0,32)) ----
        float4 v0 = xin[t];
        float4 v1 = xin[t + 256];
        float4 v2 = xin[t + 512];
        v0.x *= m; v0.y *= m; v0.z *= m; v0.w *= m;
        v1.x *= m; v1.y *= m; v1.z *= m; v1.w *= m;
        v2.x *= m; v2.y *= m; v2.z *= m; v2.w *= m;
        o[t]       = v0;
        o[t + 256] = v1;
        o[t + 512] = v2;
    } else {
        // ---- warps 1..7: pure stream ----
        const bool tail = (t >= 240);                 // warp 7 covers the 16 tail
        const int tidx = 768 + (t - 240);
        float4 v0 = xin[t];
        float4 v1 = xin[t + 256];
        float4 v2 = xin[t + 512];
        float4 v3;
        if (tail) v3 = xin[tidx];

        // spin on block-local smem flag (backoff keeps issue slots free)
        while (s_flag != (unsigned)nc) { __nanosleep(32); }
        __threadfence_block();
        const float m = s_m;

        v0.x *= m; v0.y *= m; v0.z *= m; v0.w *= m;
        v1.x *= m; v1.y *= m; v1.z *= m; v1.w *= m;
        v2.x *= m; v2.y *= m; v2.z *= m; v2.w *= m;
        o[t]       = v0;
        o[t + 256] = v1;
        o[t + 512] = v2;
        if (tail) {
            v3.x *= m; v3.y *= m; v3.z *= m; v3.w *= m;
            o[tidx] = v3;
        }
    }
}

extern "C" void kernel_launch(void* const* d_in, const int* in_sizes, int n_in,
                              void* d_out, int out_size) {
    const float* x      = (const float*)d_in[0];  // [64,256,56,56]
    const float* embeds = (const float*)d_in[1];  // [64,16]
    const float* table  = (const float*)d_in[2];  // [16,256]
    float* out = (float*)d_out;

    fused_kernel<<<NN * CC, 256>>>((const float4*)x, embeds, table, (float4*)out);
}

// round 15
// speedup vs baseline: 1.0517x; 1.0517x over previous
#include <cuda_runtime.h>

// Problem constants (from reference)
#define NN 64
#define CC 256
#define EMBED 16
#define INDEX_K 16              // ceil(256^0.5) = 16
#define HW4 784                 // float4 per (n,c) slab (56*56/4)
#define SCALE (256.0f / 240.0f) // c / (c - INDEX)

#define WPB 4                   // warps per block = slabs per block
#define TPB (WPB * 32)          // 128 threads
#define NBLK (NN * CC / WPB)    // 4096 blocks

// Block = 4 warps, 4 contiguous channels of one sample.
// Phase 1 (threads 0..63): vectorized activ for ALL 256 channels -> s_act.
// ONE __syncthreads. Phase 2: warp w computes its own channel's keep from
// s_act (LDS.128 + reduce_add, no barrier), then streams its 784-float4 slab
// alone -> per-warp self-paced loads/stores, zero post-barrier recoupling.
__global__ void __launch_bounds__(TPB)
fused_kernel(const float4* __restrict__ x,
             const float* __restrict__ embeds,
             const float* __restrict__ table,
             float4* __restrict__ out) {
    __shared__ float s_act[CC];

    const int blk = blockIdx.x;
    const int n  = blk >> 6;          // 64 blocks per sample
    const int c0 = (blk & 63) << 2;   // first of this block's 4 channels
    const int t  = threadIdx.x;
    const int w  = t >> 5;            // warp id = slab id
    const int lane = t & 31;

    // ---- phase 1: activations for all 256 channels (threads 0..63) ----
    if (t < 64) {
        const float4* __restrict__ tab4 = (const float4*)table;  // [16][64]
        const float* __restrict__ emb = embeds + n * EMBED;
        float ax = 0.f, ay = 0.f, az = 0.f, aw = 0.f;
#pragma unroll
        for (int e = 0; e < EMBED; ++e) {
            const float we = __ldg(emb + e);                // uniform broadcast
            const float4 tv = __ldg(tab4 + e * 64 + t);     // LDG.128, L1-hot
            ax += we * tv.x; ay += we * tv.y; az += we * tv.z; aw += we * tv.w;
        }
        float4 r; r.x = ax; r.y = ay; r.z = az; r.w = aw;
        ((float4*)s_act)[t] = r;
    }
    __syncthreads();   // the ONLY barrier

    // ---- phase 2a: warp-private keep for channel c0+w ----
    const float ac = s_act[c0 + w];                     // LDS broadcast
    const float4 q0 = ((const float4*)s_act)[lane * 2];      // s_act[8l..8l+3]
    const float4 q1 = ((const float4*)s_act)[lane * 2 + 1];  // s_act[8l+4..8l+7]
    int cnt8 = (q0.x <= ac) + (q0.y <= ac) + (q0.z <= ac) + (q0.w <= ac)
             + (q1.x <= ac) + (q1.y <= ac) + (q1.z <= ac) + (q1.w <= ac);
    // keep <=> #{j: activ[j] <= activ[c]} >= INDEX_K+1 (tie-safe == sorted[16] <= activ[c])
    const int cnt = __reduce_add_sync(0xffffffffu, cnt8);
    const float m = (cnt >= INDEX_K + 1) ? SCALE : 0.0f;

    // ---- phase 2b: stream this warp's slab alone (784 = 24*32 + 16) ----
    const long long base = ((long long)(n * CC + c0 + w)) * HW4;
    const float4* __restrict__ xin = x + base;
    float4* __restrict__ o = out + base;

#pragma unroll
    for (int i = 0; i < 768; i += 128) {           // 6 iterations, MLP=4
        const int i0 = i + lane;
        float4 v0 = xin[i0];
        float4 v1 = xin[i0 + 32];
        float4 v2 = xin[i0 + 64];
        float4 v3 = xin[i0 + 96];
        v0.x *= m; v0.y *= m; v0.z *= m; v0.w *= m;
        v1.x *= m; v1.y *= m; v1.z *= m; v1.w *= m;
        v2.x *= m; v2.y *= m; v2.z *= m; v2.w *= m;
        v3.x *= m; v3.y *= m; v3.z *= m; v3.w *= m;
        o[i0]      = v0;
        o[i0 + 32] = v1;
        o[i0 + 64] = v2;
        o[i0 + 96] = v3;
    }
    if (lane < 16) {                               // slab tail
        const int i0 = 768 + lane;
        float4 v = xin[i0];
        v.x *= m; v.y *= m; v.z *= m; v.w *= m;
        o[i0] = v;
    }
}

extern "C" void kernel_launch(void* const* d_in, const int* in_sizes, int n_in,
                              void* d_out, int out_size) {
    const float* x      = (const float*)d_in[0];  // [64,256,56,56]
    const float* embeds = (const float*)d_in[1];  // [64,16]
    const float* table  = (const float*)d_in[2];  // [16,256]
    float* out = (float*)d_out;

    fused_kernel<<<NBLK, TPB>>>((const float4*)x, embeds, table, (float4*)out);
}

// round 16
// speedup vs baseline: 1.0922x; 1.0385x over previous
#include <cuda_runtime.h>

// Problem constants (from reference)
#define NN 64
#define CC 256
#define EMBED 16
#define INDEX_K 16              // ceil(256^0.5) = 16
#define HW4 784                 // float4 per (n,c) slab (56*56/4)
#define SCALE (256.0f / 240.0f) // c / (c - INDEX)

// One block per (n,c) slab, 256 threads. The mask is FULLY resolved
// (both barriers included) BEFORE any x-load is issued, so the load->store
// stream runs with zero synchronization — structurally identical to the
// measured 79%-DRAM pure scale kernel. The ~300-cycle mask prolog is hidden
// by the ~7 other resident blocks per SM that are mid-stream.
__global__ void __launch_bounds__(256)
fused_kernel(const float4* __restrict__ x,
             const float* __restrict__ embeds,
             const float* __restrict__ table,
             float4* __restrict__ out) {
    __shared__ float s_act[CC];

    const int nc = blockIdx.x;
    const int n = nc >> 8;       // sample
    const int c = nc & 255;      // this block's channel
    const int t = threadIdx.x;

    // ---- mask prolog: vectorized activations (threads 0..63, LDG.128) ----
    if (t < 64) {
        const float4* __restrict__ tab4 = (const float4*)table;  // [16][64]
        const float* __restrict__ emb = embeds + n * EMBED;
        float ax = 0.f, ay = 0.f, az = 0.f, aw = 0.f;
#pragma unroll
        for (int e = 0; e < EMBED; ++e) {
            const float we = __ldg(emb + e);                // uniform broadcast
            const float4 tv = __ldg(tab4 + e * 64 + t);     // L1-hot after blk 1
            ax += we * tv.x; ay += we * tv.y; az += we * tv.z; aw += we * tv.w;
        }
        float4 r; r.x = ax; r.y = ay; r.z = az; r.w = aw;
        ((float4*)s_act)[t] = r;
    }
    __syncthreads();
    const float a = s_act[t];
    const float ac = s_act[c];
    // keep <=> #{j: activ[j] <= activ[c]} >= INDEX_K+1 (tie-safe == sorted[16] <= activ[c])
    const int cnt = __syncthreads_count(a <= ac);
    const float m = (cnt >= INDEX_K + 1) ? SCALE : 0.0f;
    // ---- mask fully resolved; no synchronization from here on ----

    const long long base = (long long)nc * HW4;
    const float4* __restrict__ xin = x + base;
    float4* __restrict__ o = out + base;

    // front-batch all DRAM loads (784 = 3*256 + 16)
    const bool tail = (t < 16);
    float4 v0 = xin[t];
    float4 v1 = xin[t + 256];
    float4 v2 = xin[t + 512];
    float4 v3;
    if (tail) v3 = xin[t + 768];

    v0.x *= m; v0.y *= m; v0.z *= m; v0.w *= m;
    v1.x *= m; v1.y *= m; v1.z *= m; v1.w *= m;
    v2.x *= m; v2.y *= m; v2.z *= m; v2.w *= m;
    o[t]       = v0;
    o[t + 256] = v1;
    o[t + 512] = v2;
    if (tail) {
        v3.x *= m; v3.y *= m; v3.z *= m; v3.w *= m;
        o[t + 768] = v3;
    }
}

extern "C" void kernel_launch(void* const* d_in, const int* in_sizes, int n_in,
                              void* d_out, int out_size) {
    const float* x      = (const float*)d_in[0];  // [64,256,56,56]
    const float* embeds = (const float*)d_in[1];  // [64,16]
    const float* table  = (const float*)d_in[2];  // [16,256]
    float* out = (float*)d_out;

    fused_kernel<<<NN * CC, 256>>>((const float4*)x, embeds, table, (float4*)out);
}

// round 17
// speedup vs baseline: 1.0986x; 1.0059x over previous
#include <cuda_runtime.h>

// Problem constants (from reference)
#define NN 64
#define CC 256
#define EMBED 16
#define INDEX_K 16              // ceil(256^0.5) = 16
#define HW4 784                 // float4 per (n,c) slab (56*56/4)
#define SCALE (256.0f / 240.0f) // c / (c - INDEX)

// One block per (n,c) slab, 256 threads.
// Mask fully resolved first (R16 ordering); then a block-uniform branch:
//   keep: front-batched float4 load -> scale -> store (proven stream body)
//   drop: pure zero stores — the x read is skipped entirely.
// 16/256 channels are dropped => ~6.25% of all reads eliminated (~13 MB/call)
// and drop-blocks retire early, freeing SM slots for streaming blocks.
__global__ void __launch_bounds__(256)
fused_kernel(const float4* __restrict__ x,
             const float* __restrict__ embeds,
             const float* __restrict__ table,
             float4* __restrict__ out) {
    __shared__ float s_act[CC];

    const int nc = blockIdx.x;
    const int n = nc >> 8;       // sample
    const int c = nc & 255;      // this block's channel
    const int t = threadIdx.x;

    // ---- mask prolog: vectorized activations (threads 0..63, LDG.128) ----
    if (t < 64) {
        const float4* __restrict__ tab4 = (const float4*)table;  // [16][64]
        const float* __restrict__ emb = embeds + n * EMBED;
        float ax = 0.f, ay = 0.f, az = 0.f, aw = 0.f;
#pragma unroll
        for (int e = 0; e < EMBED; ++e) {
            const float we = __ldg(emb + e);                // uniform broadcast
            const float4 tv = __ldg(tab4 + e * 64 + t);     // L1-hot after blk 1
            ax += we * tv.x; ay += we * tv.y; az += we * tv.z; aw += we * tv.w;
        }
        float4 r; r.x = ax; r.y = ay; r.z = az; r.w = aw;
        ((float4*)s_act)[t] = r;
    }
    __syncthreads();
    const float a = s_act[t];
    const float ac = s_act[c];
    // keep <=> #{j: activ[j] <= activ[c]} >= INDEX_K+1 (tie-safe == sorted[16] <= activ[c])
    const int cnt = __syncthreads_count(a <= ac);

    const long long base = (long long)nc * HW4;
    float4* __restrict__ o = out + base;
    const bool tail = (t < 16);                  // 784 = 3*256 + 16

    if (cnt >= INDEX_K + 1) {
        // ---- keep path: stream with no further synchronization ----
        const float4* __restrict__ xin = x + base;
        float4 v0 = xin[t];
        float4 v1 = xin[t + 256];
        float4 v2 = xin[t + 512];
        float4 v3;
        if (tail) v3 = xin[t + 768];

        v0.x *= SCALE; v0.y *= SCALE; v0.z *= SCALE; v0.w *= SCALE;
        v1.x *= SCALE; v1.y *= SCALE; v1.z *= SCALE; v1.w *= SCALE;
        v2.x *= SCALE; v2.y *= SCALE; v2.z *= SCALE; v2.w *= SCALE;
        o[t]       = v0;
        o[t + 256] = v1;
        o[t + 512] = v2;
        if (tail) {
            v3.x *= SCALE; v3.y *= SCALE; v3.z *= SCALE; v3.w *= SCALE;
            o[t + 768] = v3;
        }
    } else {
        // ---- drop path: write zeros, never read x ----
        const float4 z = make_float4(0.f, 0.f, 0.f, 0.f);
        o[t]       = z;
        o[t + 256] = z;
        o[t + 512] = z;
        if (tail) o[t + 768] = z;
    }
}

extern "C" void kernel_launch(void* const* d_in, const int* in_sizes, int n_in,
                              void* d_out, int out_size) {
    const float* x      = (const float*)d_in[0];  // [64,256,56,56]
    const float* embeds = (const float*)d_in[1];  // [64,16]
    const float* table  = (const float*)d_in[2];  // [16,256]
    float* out = (float*)d_out;

    fused_kernel<<<NN * CC, 256>>>((const float4*)x, embeds, table, (float4*)out);
}